// round 5
// baseline (speedup 1.0000x reference)
#include <cuda_runtime.h>

// CTC batch cost (Keras ctc_batch_cost), blank = V-1.
// B=256, T=512, V=256, L=64, S=129.
//
// One WARP per batch element. Lane l owns extended states {4l..4l+3}; lane 31
// also owns state 128. DP in PROBABILITY domain with PER-LANE power-of-2
// exponent frames (E[lane]), rescaled every 8 steps. The cross-lane value
// (neighbor's a3) is re-framed by 2^(E_prev - E_me), split into two clamped
// fp32 factors fixed per group. Zero lanes adopt the nearest nonzero lane's
// frame via a lane-tagged max-scan so frontier mass propagates at full
// precision. Inner loop: 1 shuffle + FMA-pipe ops only. No smem, no barriers.

#define B_      256
#define T_      512
#define V_      256
#define L_      64
#define BLANK_  (V_ - 1)
#define EPS_    1e-7f
#define PF      16
#define FULL_   0xffffffffu

__device__ __forceinline__ float exp2i_clamped(int k) {
    k = max(-126, min(127, k));
    return __int_as_float((k + 127) << 23);
}

__global__ __launch_bounds__(32)
void ctc_kernel(const int* __restrict__ y_true,
                const float* __restrict__ y_pred,
                float* __restrict__ out)
{
    const int b    = blockIdx.x;
    const int lane = threadIdx.x;

    // Labels: state 4l+1 -> y[2l], state 4l+3 -> y[2l+1]
    const int lab0  = y_true[b * L_ + 2 * lane];
    const int lab1  = y_true[b * L_ + 2 * lane + 1];
    const int labm1 = __shfl_up_sync(FULL_, lab1, 1);              // y[2l-1]
    const float sk1 = (lane == 0) ? 1.0f : ((lab0 != labm1) ? 1.0f : 0.0f);
    const float sk3 = (lab1 != lab0) ? 1.0f : 0.0f;

    const float* __restrict__ base = y_pred + (size_t)b * (T_ * V_);

    // Prefetch rings (raw probs) for blank / label0 / label1 columns.
    float qb[PF], q1[PF], q3[PF];
#pragma unroll
    for (int i = 0; i < PF; i++) {
        qb[i] = __ldcs(base + i * V_ + BLANK_);
        q1[i] = __ldcs(base + i * V_ + lab0);
        q3[i] = __ldcs(base + i * V_ + lab1);
    }

    float a0, a1, a2 = 0.f, a3 = 0.f, a4 = 0.f;
    int   E  = 0;                                   // per-lane frame: true = val * 2^E
    float s1 = (lane == 0) ? 0.f : 1.f, s2 = 1.f;   // incoming-a3 reframe factors

#define STEP(pvb, pv1, pv3) do {                                   \
        const float _pb = (pvb) + EPS_;                            \
        const float _p1 = (pv1) + EPS_;                            \
        const float _p3 = (pv3) + EPS_;                            \
        const float a3p = __shfl_up_sync(FULL_, a3, 1);            \
        const float a3q = (a3p * s1) * s2;                         \
        const float n0 = (a0 + a3q) * _pb;                         \
        const float n1 = fmaf(sk1, a3q, a0 + a1) * _p1;            \
        const float n2 = (a1 + a2) * _pb;                          \
        const float n3 = fmaf(sk3, a1, a2 + a3) * _p3;             \
        const float n4 = (a3 + a4) * _pb;                          \
        a0 = n0; a1 = n1; a2 = n2; a3 = n3; a4 = n4;               \
    } while (0)

#define RESCALE() do {                                             \
        float m = fmaxf(fmaxf(a0, a1), fmaxf(a2, a3));             \
        m = fmaxf(m, a4);                                          \
        const bool nz = (m > 0.f);                                 \
        if (nz) {                                                  \
            const int e  = ilogbf(m);                              \
            const int h1 = e >> 1, h2 = e - h1;                    \
            const float u1 = exp2i_clamped(-h1);                   \
            const float u2 = exp2i_clamped(-h2);                   \
            a0 = (a0 * u1) * u2; a1 = (a1 * u1) * u2;              \
            a2 = (a2 * u1) * u2; a3 = (a3 * u1) * u2;              \
            a4 = (a4 * u1) * u2;                                   \
            E += e;                                                \
        }                                                          \
        /* zero lanes adopt nearest-left nonzero lane's frame:     \
           lane-tagged inclusive max-scan */                       \
        int key = nz ? ((lane << 15) | (E + 16384)) : -1;          \
        _Pragma("unroll")                                          \
        for (int off = 1; off < 32; off <<= 1) {                   \
            const int kl = __shfl_up_sync(FULL_, key, off);        \
            if (lane >= off) key = max(key, kl);                   \
        }                                                          \
        if (!nz) E = (key & 32767) - 16384;                        \
        const int Ep = __shfl_up_sync(FULL_, E, 1);                \
        const int dE = Ep - E;                                     \
        const int d1 = dE >> 1, d2 = dE - d1;                      \
        s1 = (lane == 0) ? 0.f : exp2i_clamped(d1);                \
        s2 = exp2i_clamped(d2);                                    \
    } while (0)

    // ---- group 0: t=0 init, t=1..15 steps, refill t=16..31 ----
    a0 = (lane == 0) ? (qb[0] + EPS_) : 0.f;
    a1 = (lane == 0) ? (q1[0] + EPS_) : 0.f;
    qb[0] = __ldcs(base + PF * V_ + BLANK_);
    q1[0] = __ldcs(base + PF * V_ + lab0);
    q3[0] = __ldcs(base + PF * V_ + lab1);
#pragma unroll
    for (int i = 1; i < PF; i++) {
        STEP(qb[i], q1[i], q3[i]);
        qb[i] = __ldcs(base + (i + PF) * V_ + BLANK_);
        q1[i] = __ldcs(base + (i + PF) * V_ + lab0);
        q3[i] = __ldcs(base + (i + PF) * V_ + lab1);
        if (i == 7 || i == 15) RESCALE();
    }

    // ---- middle groups ----
#pragma unroll 1
    for (int tt = PF; tt < T_ - PF; tt += PF) {
#pragma unroll
        for (int i = 0; i < PF; i++) {
            STEP(qb[i], q1[i], q3[i]);
            const int tn = tt + i + PF;
            qb[i] = __ldcs(base + tn * V_ + BLANK_);
            q1[i] = __ldcs(base + tn * V_ + lab0);
            q3[i] = __ldcs(base + tn * V_ + lab1);
            if (i == 7 || i == 15) RESCALE();
        }
    }

    // ---- last group: t = T-16 .. T-1, no refill, no rescale needed ----
#pragma unroll
    for (int i = 0; i < PF; i++) {
        STEP(qb[i], q1[i], q3[i]);
    }

    // loss = -( log(alpha[127] + alpha[128]) + E*ln2 ), states on lane 31
    if (lane == 31) {
        const float tot = a3 + a4;
        out[b] = -(logf(tot) + (float)E * 0.6931471805599453f);
    }

#undef STEP
#undef RESCALE
}

extern "C" void kernel_launch(void* const* d_in, const int* in_sizes, int n_in,
                              void* d_out, int out_size) {
    const int*   y_true = (const int*)  d_in[0];
    const float* y_pred = (const float*)d_in[1];
    float*       out    = (float*)      d_out;
    ctc_kernel<<<B_, 32>>>(y_true, y_pred, out);
}

// round 6
// speedup vs baseline: 1.0520x; 1.0520x over previous
#include <cuda_runtime.h>
#include <cstdint>

// CTC batch cost (Keras ctc_batch_cost), blank = V-1.
// B=256, T=512, V=256, L=64, S=129.
//
// One WARP per batch element; lane l owns states {4l..4l+3}, lane 31 also
// state 128. Probability-domain DP with per-lane power-of-2 frames (R5 math).
// NEW: gathers go through a cp.async (LDGSTS) shared-memory ring, 8 chunks of
// 8 time steps. LDGSTS has no per-warp outstanding cap, so ~50KB/warp stays
// in flight (~13MB chip-wide) -> DRAM saturation instead of the 55-LDG MLP
// cap that held R5 at 42% of HBM. Frontier scan only for t<64 (all 129
// states reachable after that); scan-free rescale afterwards.

#define B_      256
#define T_      512
#define V_      256
#define L_      64
#define BLANK_  (V_ - 1)
#define EPS_    1e-7f
#define FULL_   0xffffffffu
#define CHUNK   8
#define RING    8
#define NCHUNK  (T_ / CHUNK)   // 64

__device__ __forceinline__ uint32_t smem_u32(const void* p) {
    return (uint32_t)__cvta_generic_to_shared(p);
}
__device__ __forceinline__ void cpa4(uint32_t s, const float* g) {
    asm volatile("cp.async.ca.shared.global [%0], [%1], 4;" :: "r"(s), "l"(g));
}
__device__ __forceinline__ void cpa_commit() {
    asm volatile("cp.async.commit_group;" ::: "memory");
}
__device__ __forceinline__ void cpa_wait(int n) {
    switch (n) {
      case 0: asm volatile("cp.async.wait_group 0;" ::: "memory"); break;
      case 1: asm volatile("cp.async.wait_group 1;" ::: "memory"); break;
      case 2: asm volatile("cp.async.wait_group 2;" ::: "memory"); break;
      case 3: asm volatile("cp.async.wait_group 3;" ::: "memory"); break;
      case 4: asm volatile("cp.async.wait_group 4;" ::: "memory"); break;
      case 5: asm volatile("cp.async.wait_group 5;" ::: "memory"); break;
      default: asm volatile("cp.async.wait_group 6;" ::: "memory"); break;
    }
}
__device__ __forceinline__ float exp2i_clamped(int k) {
    k = max(-126, min(127, k));
    return __int_as_float((k + 127) << 23);
}

__global__ __launch_bounds__(32)
void ctc_kernel(const int* __restrict__ y_true,
                const float* __restrict__ y_pred,
                float* __restrict__ out)
{
    __shared__ float2 Q[RING][CHUNK][32];   // (q1,q3) per lane per step
    __shared__ float  QB[RING][CHUNK];      // blank prob per step

    const int b    = blockIdx.x;
    const int lane = threadIdx.x;

    const int lab0  = y_true[b * L_ + 2 * lane];
    const int lab1  = y_true[b * L_ + 2 * lane + 1];
    const int labm1 = __shfl_up_sync(FULL_, lab1, 1);
    const float sk1 = (lane == 0) ? 1.0f : ((lab0 != labm1) ? 1.0f : 0.0f);
    const float sk3 = (lab1 != lab0) ? 1.0f : 0.0f;

    const float* __restrict__ base = y_pred + (size_t)b * (T_ * V_);

    const uint32_t sQ  = smem_u32(&Q[0][0][0]);
    const uint32_t sQB = smem_u32(&QB[0][0]);

#define ISSUE(c) do {                                                  \
        const int _slot = (c) & (RING - 1);                            \
        const float* _g = base + (c) * (CHUNK * V_);                   \
        const uint32_t _dst = sQ + _slot * (CHUNK * 32 * 8) + lane * 8;\
        _Pragma("unroll")                                              \
        for (int _i = 0; _i < CHUNK; _i++) {                           \
            cpa4(_dst + _i * (32 * 8) + 0, _g + _i * V_ + lab0);       \
            cpa4(_dst + _i * (32 * 8) + 4, _g + _i * V_ + lab1);       \
        }                                                              \
        if (lane < CHUNK)                                              \
            cpa4(sQB + _slot * (CHUNK * 4) + lane * 4,                 \
                 _g + lane * V_ + BLANK_);                             \
        cpa_commit();                                                  \
    } while (0)

    // ---- prefill ring: chunks 0..6 ----
#pragma unroll
    for (int c = 0; c < RING - 1; c++) ISSUE(c);

    float a0 = 0.f, a1 = 0.f, a2 = 0.f, a3 = 0.f, a4 = 0.f;
    int   E  = 0;
    float s1 = (lane == 0) ? 0.f : 1.f, s2 = 1.f;

#define STEP(pvb, pv1, pv3) do {                                   \
        const float _pb = (pvb) + EPS_;                            \
        const float _p1 = (pv1) + EPS_;                            \
        const float _p3 = (pv3) + EPS_;                            \
        const float a3p = __shfl_up_sync(FULL_, a3, 1);            \
        const float a3q = (a3p * s1) * s2;                         \
        const float n0 = (a0 + a3q) * _pb;                         \
        const float n1 = fmaf(sk1, a3q, a0 + a1) * _p1;            \
        const float n2 = (a1 + a2) * _pb;                          \
        const float n3 = fmaf(sk3, a1, a2 + a3) * _p3;             \
        const float n4 = (a3 + a4) * _pb;                          \
        a0 = n0; a1 = n1; a2 = n2; a3 = n3; a4 = n4;               \
    } while (0)

#define NEIGHBOR_FACTORS() do {                                    \
        const int Ep = __shfl_up_sync(FULL_, E, 1);                \
        const int dE = Ep - E;                                     \
        const int d1 = dE >> 1, d2 = dE - d1;                      \
        s1 = (lane == 0) ? 0.f : exp2i_clamped(d1);                \
        s2 = exp2i_clamped(d2);                                    \
    } while (0)

    // Startup rescale (t < 64): zero lanes adopt nearest-left nonzero frame.
#define RESCALE_SCAN() do {                                        \
        float m = fmaxf(fmaxf(a0, a1), fmaxf(a2, a3));             \
        m = fmaxf(m, a4);                                          \
        const bool nz = (m > 0.f);                                 \
        if (nz) {                                                  \
            const int e  = ilogbf(m);                              \
            const int h1 = e >> 1, h2 = e - h1;                    \
            const float u1 = exp2i_clamped(-h1);                   \
            const float u2 = exp2i_clamped(-h2);                   \
            a0 = (a0 * u1) * u2; a1 = (a1 * u1) * u2;              \
            a2 = (a2 * u1) * u2; a3 = (a3 * u1) * u2;              \
            a4 = (a4 * u1) * u2;                                   \
            E += e;                                                \
        }                                                          \
        int key = nz ? ((lane << 15) | (E + 16384)) : -1;          \
        _Pragma("unroll")                                          \
        for (int off = 1; off < 32; off <<= 1) {                   \
            const int kl = __shfl_up_sync(FULL_, key, off);        \
            if (lane >= off) key = max(key, kl);                   \
        }                                                          \
        if (!nz) E = (key & 32767) - 16384;                        \
        NEIGHBOR_FACTORS();                                        \
    } while (0)

    // Steady-state rescale (t >= 64): every lane has nonzero mass.
#define RESCALE_FAST() do {                                        \
        float m = fmaxf(fmaxf(a0, a1), fmaxf(a2, a3));             \
        m = fmaxf(m, a4);                                          \
        const int e  = ilogbf(m);                                  \
        const int h1 = e >> 1, h2 = e - h1;                        \
        const float u1 = exp2i_clamped(-h1);                       \
        const float u2 = exp2i_clamped(-h2);                       \
        a0 = (a0 * u1) * u2; a1 = (a1 * u1) * u2;                  \
        a2 = (a2 * u1) * u2; a3 = (a3 * u1) * u2;                  \
        a4 = (a4 * u1) * u2;                                       \
        E += e;                                                    \
        NEIGHBOR_FACTORS();                                        \
    } while (0)

    // ---- chunk 0: wait, read, init t=0, steps 1..7 ----
    {
        cpa_wait(6);
        __syncwarp();
        float2 v[CHUNK]; float vb[CHUNK];
#pragma unroll
        for (int i = 0; i < CHUNK; i++) { v[i] = Q[0][i][lane]; vb[i] = QB[0][i]; }
        ISSUE(7);

        a0 = (lane == 0) ? (vb[0]   + EPS_) : 0.f;
        a1 = (lane == 0) ? (v[0].x  + EPS_) : 0.f;
#pragma unroll
        for (int i = 1; i < CHUNK; i++) STEP(vb[i], v[i].x, v[i].y);
        RESCALE_SCAN();
    }

    // ---- main loop: chunks 1..63 ----
#pragma unroll 1
    for (int c = 1; c < NCHUNK; c++) {
        const int rem = NCHUNK - 1 - c;
        cpa_wait(rem > 6 ? 6 : rem);
        __syncwarp();
        const int slot = c & (RING - 1);
        float2 v[CHUNK]; float vb[CHUNK];
#pragma unroll
        for (int i = 0; i < CHUNK; i++) { v[i] = Q[slot][i][lane]; vb[i] = QB[slot][i]; }
        if (c + RING - 1 < NCHUNK) ISSUE(c + RING - 1);

#pragma unroll
        for (int i = 0; i < CHUNK; i++) STEP(vb[i], v[i].x, v[i].y);

        if (c < NCHUNK - 1) {
            if (c < 8) RESCALE_SCAN();
            else       RESCALE_FAST();
        }
    }

    // loss = -( log(alpha[127] + alpha[128]) + E*ln2 ), both on lane 31
    if (lane == 31) {
        const float tot = a3 + a4;
        out[b] = -(logf(tot) + (float)E * 0.6931471805599453f);
    }

#undef STEP
#undef NEIGHBOR_FACTORS
#undef RESCALE_SCAN
#undef RESCALE_FAST
#undef ISSUE
}

extern "C" void kernel_launch(void* const* d_in, const int* in_sizes, int n_in,
                              void* d_out, int out_size) {
    const int*   y_true = (const int*)  d_in[0];
    const float* y_pred = (const float*)d_in[1];
    float*       out    = (float*)      d_out;
    ctc_kernel<<<B_, 32>>>(y_true, y_pred, out);
}

// round 8
// speedup vs baseline: 1.2357x; 1.1746x over previous
#include <cuda_runtime.h>
#include <cstdint>

// CTC batch cost (Keras ctc_batch_cost), blank = V-1.
// B=256, T=512, V=256, L=64, S=129.
//
// One WARP per batch element; lane l owns states {4l..4l+3}, lane 31 also
// state 128. Probability-domain DP with per-lane power-of-2 frames.
//
// R7: the t-row gathers were L1tex-wavefront-bound (scattered 4B cp.asyncs =
// ~30 wavefronts/step carrying 4B each). Since sector-granular traffic already
// pulled ~the whole tensor, now load each FULL 1KB row coalesced via
// 2x16B cp.async.cg per lane (8 wavefronts/row) into a 4-deep smem ring of
// 8-row chunks, and do the per-step gather with LDS (cheap, conflict ~3-way).

#define B_      256
#define T_      512
#define V_      256
#define L_      64
#define BLANK_  (V_ - 1)
#define EPS_    1e-7f
#define FULL_   0xffffffffu
#define CHUNK   8
#define RING    4
#define NCHUNK  (T_ / CHUNK)   // 64

__device__ __forceinline__ uint32_t smem_u32(const void* p) {
    return (uint32_t)__cvta_generic_to_shared(p);
}
__device__ __forceinline__ void cpa16(uint32_t s, const float* g) {
    asm volatile("cp.async.cg.shared.global [%0], [%1], 16;" :: "r"(s), "l"(g));
}
__device__ __forceinline__ void cpa_commit() {
    asm volatile("cp.async.commit_group;" ::: "memory");
}
__device__ __forceinline__ void cpa_wait(int n) {
    switch (n) {
      case 0: asm volatile("cp.async.wait_group 0;" ::: "memory"); break;
      case 1: asm volatile("cp.async.wait_group 1;" ::: "memory"); break;
      default: asm volatile("cp.async.wait_group 2;" ::: "memory"); break;
    }
}
__device__ __forceinline__ float exp2i_clamped(int k) {
    k = max(-126, min(127, k));
    return __int_as_float((k + 127) << 23);
}

__global__ __launch_bounds__(32)
void ctc_kernel(const int* __restrict__ y_true,
                const float* __restrict__ y_pred,
                float* __restrict__ out)
{
    __shared__ float ROW[RING][CHUNK][V_];   // 4 * 8 * 1KB = 32KB

    const int b    = blockIdx.x;
    const int lane = threadIdx.x;

    const int lab0  = y_true[b * L_ + 2 * lane];
    const int lab1  = y_true[b * L_ + 2 * lane + 1];
    const int labm1 = __shfl_up_sync(FULL_, lab1, 1);
    const float sk1 = (lane == 0) ? 1.0f : ((lab0 != labm1) ? 1.0f : 0.0f);
    const float sk3 = (lab1 != lab0) ? 1.0f : 0.0f;

    const float* __restrict__ base = y_pred + (size_t)b * (T_ * V_);

    const uint32_t sROW = smem_u32(&ROW[0][0][0]);

    // Coalesced full-row fetch: lane covers floats [4*lane,4*lane+4) and
    // [128+4*lane, 128+4*lane+4) of each 256-float row.
#define ISSUE(c) do {                                                    \
        const int _slot = (c) & (RING - 1);                              \
        const float* _g = base + (c) * (CHUNK * V_) + lane * 4;          \
        const uint32_t _dst = sROW + _slot * (CHUNK * V_ * 4) + lane*16; \
        _Pragma("unroll")                                                \
        for (int _i = 0; _i < CHUNK; _i++) {                             \
            cpa16(_dst + _i * (V_ * 4) + 0,   _g + _i * V_);             \
            cpa16(_dst + _i * (V_ * 4) + 512, _g + _i * V_ + 128);       \
        }                                                                \
        cpa_commit();                                                    \
    } while (0)

    // ---- prefill ring: chunks 0..2 ----
#pragma unroll
    for (int c = 0; c < RING - 1; c++) ISSUE(c);

    float a0 = 0.f, a1 = 0.f, a2 = 0.f, a3 = 0.f, a4 = 0.f;
    int   E  = 0;
    float s1 = (lane == 0) ? 0.f : 1.f, s2 = 1.f;

#define STEP(pvb, pv1, pv3) do {                                   \
        const float _pb = (pvb) + EPS_;                            \
        const float _p1 = (pv1) + EPS_;                            \
        const float _p3 = (pv3) + EPS_;                            \
        const float a3p = __shfl_up_sync(FULL_, a3, 1);            \
        const float a3q = (a3p * s1) * s2;                         \
        const float n0 = (a0 + a3q) * _pb;                         \
        const float n1 = fmaf(sk1, a3q, a0 + a1) * _p1;            \
        const float n2 = (a1 + a2) * _pb;                          \
        const float n3 = fmaf(sk3, a1, a2 + a3) * _p3;             \
        const float n4 = (a3 + a4) * _pb;                          \
        a0 = n0; a1 = n1; a2 = n2; a3 = n3; a4 = n4;               \
    } while (0)

#define NEIGHBOR_FACTORS() do {                                    \
        const int Ep = __shfl_up_sync(FULL_, E, 1);                \
        const int dE = Ep - E;                                     \
        const int d1 = dE >> 1, d2 = dE - d1;                      \
        s1 = (lane == 0) ? 0.f : exp2i_clamped(d1);                \
        s2 = exp2i_clamped(d2);                                    \
    } while (0)

    // Startup rescale (t < 64): zero lanes adopt nearest-left nonzero frame.
#define RESCALE_SCAN() do {                                        \
        float m = fmaxf(fmaxf(a0, a1), fmaxf(a2, a3));             \
        m = fmaxf(m, a4);                                          \
        const bool nz = (m > 0.f);                                 \
        if (nz) {                                                  \
            const int e  = ilogbf(m);                              \
            const int h1 = e >> 1, h2 = e - h1;                    \
            const float u1 = exp2i_clamped(-h1);                   \
            const float u2 = exp2i_clamped(-h2);                   \
            a0 = (a0 * u1) * u2; a1 = (a1 * u1) * u2;              \
            a2 = (a2 * u1) * u2; a3 = (a3 * u1) * u2;              \
            a4 = (a4 * u1) * u2;                                   \
            E += e;                                                \
        }                                                          \
        int key = nz ? ((lane << 15) | (E + 16384)) : -1;          \
        _Pragma("unroll")                                          \
        for (int off = 1; off < 32; off <<= 1) {                   \
            const int kl = __shfl_up_sync(FULL_, key, off);        \
            if (lane >= off) key = max(key, kl);                   \
        }                                                          \
        if (!nz) E = (key & 32767) - 16384;                        \
        NEIGHBOR_FACTORS();                                        \
    } while (0)

    // Steady-state rescale (t >= 64): every lane has nonzero mass.
#define RESCALE_FAST() do {                                        \
        float m = fmaxf(fmaxf(a0, a1), fmaxf(a2, a3));             \
        m = fmaxf(m, a4);                                          \
        const int e  = ilogbf(m);                                  \
        const int h1 = e >> 1, h2 = e - h1;                        \
        const float u1 = exp2i_clamped(-h1);                       \
        const float u2 = exp2i_clamped(-h2);                       \
        a0 = (a0 * u1) * u2; a1 = (a1 * u1) * u2;                  \
        a2 = (a2 * u1) * u2; a3 = (a3 * u1) * u2;                  \
        a4 = (a4 * u1) * u2;                                       \
        E += e;                                                    \
        NEIGHBOR_FACTORS();                                        \
    } while (0)

    // Per-chunk SMEM gather into registers (independent loads, pipelined).
#define GATHER(slot, v1, v3, vb) do {                              \
        _Pragma("unroll")                                          \
        for (int _i = 0; _i < CHUNK; _i++) {                       \
            (v1)[_i] = ROW[slot][_i][lab0];                        \
            (v3)[_i] = ROW[slot][_i][lab1];                        \
            (vb)[_i] = ROW[slot][_i][BLANK_];                      \
        }                                                          \
    } while (0)

    // ---- chunk 0 ----
    {
        cpa_wait(RING - 2);
        __syncwarp();
        float v1[CHUNK], v3[CHUNK], vb[CHUNK];
        GATHER(0, v1, v3, vb);
        ISSUE(RING - 1);

        a0 = (lane == 0) ? (vb[0] + EPS_) : 0.f;
        a1 = (lane == 0) ? (v1[0] + EPS_) : 0.f;
#pragma unroll
        for (int i = 1; i < CHUNK; i++) STEP(vb[i], v1[i], v3[i]);
        RESCALE_SCAN();
    }

    // ---- main loop: chunks 1..63 ----
#pragma unroll 1
    for (int c = 1; c < NCHUNK; c++) {
        const int rem = NCHUNK - 1 - c;
        cpa_wait(rem > RING - 2 ? RING - 2 : rem);
        __syncwarp();
        const int slot = c & (RING - 1);
        float v1[CHUNK], v3[CHUNK], vb[CHUNK];
        GATHER(slot, v1, v3, vb);
        if (c + RING - 1 < NCHUNK) ISSUE(c + RING - 1);

#pragma unroll
        for (int i = 0; i < CHUNK; i++) STEP(vb[i], v1[i], v3[i]);

        if (c < NCHUNK - 1) {
            if (c < 8) RESCALE_SCAN();
            else       RESCALE_FAST();
        }
    }

    // loss = -( log(alpha[127] + alpha[128]) + E*ln2 ), both on lane 31
    if (lane == 31) {
        const float tot = a3 + a4;
        out[b] = -(logf(tot) + (float)E * 0.6931471805599453f);
    }

#undef STEP
#undef NEIGHBOR_FACTORS
#undef RESCALE_SCAN
#undef RESCALE_FAST
#undef GATHER
#undef ISSUE
}

extern "C" void kernel_launch(void* const* d_in, const int* in_sizes, int n_in,
                              void* d_out, int out_size) {
    const int*   y_true = (const int*)  d_in[0];
    const float* y_pred = (const float*)d_in[1];
    float*       out    = (float*)      d_out;
    ctc_kernel<<<B_, 32>>>(y_true, y_pred, out);
}

// round 9
// speedup vs baseline: 1.4421x; 1.1670x over previous
#include <cuda_runtime.h>
#include <cstdint>

// CTC batch cost (Keras ctc_batch_cost), blank = V-1.
// B=256, T=512, V=256, L=64, S=129.
//
// R9: warp-specialized CTA (64 threads). Warp 0 = DP consumer (lane l owns
// states {4l..4l+3}, lane 31 also state 128; probability-domain DP with
// per-lane power-of-2 frames). Warp 1 = producer streaming full 1KB rows
// coalesced via cp.async.cg into a 4-deep smem ring, paced by one bar.sync
// per 8-step chunk. This decouples load issue from the DP warp's serial
// period (which capped R8's DRAM at 4.3 TB/s).

#define B_      256
#define T_      512
#define V_      256
#define L_      64
#define BLANK_  (V_ - 1)
#define EPS_    1e-7f
#define FULL_   0xffffffffu
#define CHUNK   8
#define RING    4
#define NCHUNK  (T_ / CHUNK)   // 64

__device__ __forceinline__ uint32_t smem_u32(const void* p) {
    return (uint32_t)__cvta_generic_to_shared(p);
}
__device__ __forceinline__ void cpa16(uint32_t s, const float* g) {
    asm volatile("cp.async.cg.shared.global [%0], [%1], 16;" :: "r"(s), "l"(g));
}
__device__ __forceinline__ void cpa_commit() {
    asm volatile("cp.async.commit_group;" ::: "memory");
}
__device__ __forceinline__ void cpa_wait(int n) {
    switch (n) {
      case 0: asm volatile("cp.async.wait_group 0;" ::: "memory"); break;
      case 1: asm volatile("cp.async.wait_group 1;" ::: "memory"); break;
      default: asm volatile("cp.async.wait_group 2;" ::: "memory"); break;
    }
}
__device__ __forceinline__ void barrier64() {
    asm volatile("bar.sync 0, 64;" ::: "memory");
}
__device__ __forceinline__ float exp2i_clamped(int k) {
    k = max(-126, min(127, k));
    return __int_as_float((k + 127) << 23);
}

__global__ __launch_bounds__(64)
void ctc_kernel(const int* __restrict__ y_true,
                const float* __restrict__ y_pred,
                float* __restrict__ out)
{
    __shared__ float ROW[RING][CHUNK][V_];   // 4 * 8 * 1KB = 32KB

    const int b    = blockIdx.x;
    const int lane = threadIdx.x & 31;
    const int warp = threadIdx.x >> 5;

    const float* __restrict__ base = y_pred + (size_t)b * (T_ * V_);
    const uint32_t sROW = smem_u32(&ROW[0][0][0]);

#define ISSUE(c) do {                                                    \
        const int _slot = (c) & (RING - 1);                              \
        const float* _g = base + (c) * (CHUNK * V_) + lane * 4;          \
        const uint32_t _dst = sROW + _slot * (CHUNK * V_ * 4) + lane*16; \
        _Pragma("unroll")                                                \
        for (int _i = 0; _i < CHUNK; _i++) {                             \
            cpa16(_dst + _i * (V_ * 4) + 0,   _g + _i * V_);             \
            cpa16(_dst + _i * (V_ * 4) + 512, _g + _i * V_ + 128);       \
        }                                                                \
        cpa_commit();                                                    \
    } while (0)

    if (warp == 1) {
        // ================= PRODUCER =================
#pragma unroll
        for (int c = 0; c < RING - 1; c++) ISSUE(c);   // prefill 0..2
#pragma unroll 1
        for (int c = 0; c < NCHUNK; c++) {
            const int rem = NCHUNK - 1 - c;
            cpa_wait(rem > RING - 2 ? RING - 2 : rem); // chunk c has landed
            barrier64();                               // publish to consumer
            if (c + RING - 1 < NCHUNK) ISSUE(c + RING - 1); // overwrites slot (c-1)%RING: consumer done with it
        }
        return;
    }

    // ================= CONSUMER (DP) =================
    const int lab0  = y_true[b * L_ + 2 * lane];
    const int lab1  = y_true[b * L_ + 2 * lane + 1];
    const int labm1 = __shfl_up_sync(FULL_, lab1, 1);
    const float sk1 = (lane == 0) ? 1.0f : ((lab0 != labm1) ? 1.0f : 0.0f);
    const float sk3 = (lab1 != lab0) ? 1.0f : 0.0f;

    float a0 = 0.f, a1 = 0.f, a2 = 0.f, a3 = 0.f, a4 = 0.f;
    int   E  = 0;
    float s1 = (lane == 0) ? 0.f : 1.f, s2 = 1.f;

#define STEP(pvb, pv1, pv3) do {                                   \
        const float _pb = (pvb) + EPS_;                            \
        const float _p1 = (pv1) + EPS_;                            \
        const float _p3 = (pv3) + EPS_;                            \
        const float a3p = __shfl_up_sync(FULL_, a3, 1);            \
        const float a3q = (a3p * s1) * s2;                         \
        const float n0 = (a0 + a3q) * _pb;                         \
        const float n1 = fmaf(sk1, a3q, a0 + a1) * _p1;            \
        const float n2 = (a1 + a2) * _pb;                          \
        const float n3 = fmaf(sk3, a1, a2 + a3) * _p3;             \
        const float n4 = (a3 + a4) * _pb;                          \
        a0 = n0; a1 = n1; a2 = n2; a3 = n3; a4 = n4;               \
    } while (0)

#define NEIGHBOR_FACTORS() do {                                    \
        const int Ep = __shfl_up_sync(FULL_, E, 1);                \
        const int dE = Ep - E;                                     \
        const int d1 = dE >> 1, d2 = dE - d1;                      \
        s1 = (lane == 0) ? 0.f : exp2i_clamped(d1);                \
        s2 = exp2i_clamped(d2);                                    \
    } while (0)

#define RESCALE_SCAN() do {                                        \
        float m = fmaxf(fmaxf(a0, a1), fmaxf(a2, a3));             \
        m = fmaxf(m, a4);                                          \
        const bool nz = (m > 0.f);                                 \
        if (nz) {                                                  \
            const int e  = ilogbf(m);                              \
            const int h1 = e >> 1, h2 = e - h1;                    \
            const float u1 = exp2i_clamped(-h1);                   \
            const float u2 = exp2i_clamped(-h2);                   \
            a0 = (a0 * u1) * u2; a1 = (a1 * u1) * u2;              \
            a2 = (a2 * u1) * u2; a3 = (a3 * u1) * u2;              \
            a4 = (a4 * u1) * u2;                                   \
            E += e;                                                \
        }                                                          \
        int key = nz ? ((lane << 15) | (E + 16384)) : -1;          \
        _Pragma("unroll")                                          \
        for (int off = 1; off < 32; off <<= 1) {                   \
            const int kl = __shfl_up_sync(FULL_, key, off);        \
            if (lane >= off) key = max(key, kl);                   \
        }                                                          \
        if (!nz) E = (key & 32767) - 16384;                        \
        NEIGHBOR_FACTORS();                                        \
    } while (0)

#define RESCALE_FAST() do {                                        \
        float m = fmaxf(fmaxf(a0, a1), fmaxf(a2, a3));             \
        m = fmaxf(m, a4);                                          \
        const int e  = ilogbf(m);                                  \
        const int h1 = e >> 1, h2 = e - h1;                        \
        const float u1 = exp2i_clamped(-h1);                       \
        const float u2 = exp2i_clamped(-h2);                       \
        a0 = (a0 * u1) * u2; a1 = (a1 * u1) * u2;                  \
        a2 = (a2 * u1) * u2; a3 = (a3 * u1) * u2;                  \
        a4 = (a4 * u1) * u2;                                       \
        E += e;                                                    \
        NEIGHBOR_FACTORS();                                        \
    } while (0)

#define GATHER(slot, v1, v3, vb) do {                              \
        _Pragma("unroll")                                          \
        for (int _i = 0; _i < CHUNK; _i++) {                       \
            (v1)[_i] = ROW[slot][_i][lab0];                        \
            (v3)[_i] = ROW[slot][_i][lab1];                        \
            (vb)[_i] = ROW[slot][_i][BLANK_];                      \
        }                                                          \
    } while (0)

    // ---- chunk 0 ----
    {
        barrier64();
        float v1[CHUNK], v3[CHUNK], vb[CHUNK];
        GATHER(0, v1, v3, vb);
        a0 = (lane == 0) ? (vb[0] + EPS_) : 0.f;
        a1 = (lane == 0) ? (v1[0] + EPS_) : 0.f;
#pragma unroll
        for (int i = 1; i < CHUNK; i++) STEP(vb[i], v1[i], v3[i]);
        RESCALE_SCAN();
    }

    // ---- chunks 1..63 ----
#pragma unroll 1
    for (int c = 1; c < NCHUNK; c++) {
        barrier64();
        const int slot = c & (RING - 1);
        float v1[CHUNK], v3[CHUNK], vb[CHUNK];
        GATHER(slot, v1, v3, vb);
#pragma unroll
        for (int i = 0; i < CHUNK; i++) STEP(vb[i], v1[i], v3[i]);
        if (c < NCHUNK - 1) {
            if (c < 8) RESCALE_SCAN();
            else       RESCALE_FAST();
        }
    }

    // loss = -( log(alpha[127] + alpha[128]) + E*ln2 ), both on lane 31
    if (lane == 31) {
        const float tot = a3 + a4;
        out[b] = -(logf(tot) + (float)E * 0.6931471805599453f);
    }

#undef STEP
#undef NEIGHBOR_FACTORS
#undef RESCALE_SCAN
#undef RESCALE_FAST
#undef GATHER
#undef ISSUE
}

extern "C" void kernel_launch(void* const* d_in, const int* in_sizes, int n_in,
                              void* d_out, int out_size) {
    const int*   y_true = (const int*)  d_in[0];
    const float* y_pred = (const float*)d_in[1];
    float*       out    = (float*)      d_out;
    ctc_kernel<<<B_, 64>>>(y_true, y_pred, out);
}

// round 14
// speedup vs baseline: 1.4649x; 1.0158x over previous
#include <cuda_runtime.h>
#include <cstdint>

// CTC batch cost (Keras ctc_batch_cost), blank = V-1.
// B=256, T=512, V=256, L=64, S=129.
//
// R10: warp-specialized CTA (64 threads): warp1 streams full 1KB rows
// coalesced (cp.async.cg) into a 4-deep smem ring; warp0 runs the DP.
// NEW: consumer is software-pipelined one chunk ahead — after barrier c it
// issues the LDS gather for chunk c into buffer B, then runs the 8 DP steps
// on chunk c-1 from buffer A. Gather latency + barrier overlap the serial
// STEP chain, which removes ~400 cyc/chunk of exposed latency that held R9's
// DRAM at 61%.

#define B_      256
#define T_      512
#define V_      256
#define L_      64
#define BLANK_  (V_ - 1)
#define EPS_    1e-7f
#define FULL_   0xffffffffu
#define CHUNK   8
#define RING    4
#define NCHUNK  (T_ / CHUNK)   // 64

__device__ __forceinline__ uint32_t smem_u32(const void* p) {
    return (uint32_t)__cvta_generic_to_shared(p);
}
__device__ __forceinline__ void cpa16(uint32_t s, const float* g) {
    asm volatile("cp.async.cg.shared.global [%0], [%1], 16;" :: "r"(s), "l"(g));
}
__device__ __forceinline__ void cpa_commit() {
    asm volatile("cp.async.commit_group;" ::: "memory");
}
__device__ __forceinline__ void cpa_wait(int n) {
    switch (n) {
      case 0: asm volatile("cp.async.wait_group 0;" ::: "memory"); break;
      case 1: asm volatile("cp.async.wait_group 1;" ::: "memory"); break;
      default: asm volatile("cp.async.wait_group 2;" ::: "memory"); break;
    }
}
__device__ __forceinline__ void barrier64() {
    asm volatile("bar.sync 0, 64;" ::: "memory");
}
__device__ __forceinline__ float exp2i_clamped(int k) {
    k = max(-126, min(127, k));
    return __int_as_float((k + 127) << 23);
}

__global__ __launch_bounds__(64)
void ctc_kernel(const int* __restrict__ y_true,
                const float* __restrict__ y_pred,
                float* __restrict__ out)
{
    __shared__ float ROW[RING][CHUNK][V_];   // 4 * 8 * 1KB = 32KB

    const int b    = blockIdx.x;
    const int lane = threadIdx.x & 31;
    const int warp = threadIdx.x >> 5;

    const float* __restrict__ base = y_pred + (size_t)b * (T_ * V_);
    const uint32_t sROW = smem_u32(&ROW[0][0][0]);

#define ISSUE(c) do {                                                    \
        const int _slot = (c) & (RING - 1);                              \
        const float* _g = base + (c) * (CHUNK * V_) + lane * 4;          \
        const uint32_t _dst = sROW + _slot * (CHUNK * V_ * 4) + lane*16; \
        _Pragma("unroll")                                                \
        for (int _i = 0; _i < CHUNK; _i++) {                             \
            cpa16(_dst + _i * (V_ * 4) + 0,   _g + _i * V_);             \
            cpa16(_dst + _i * (V_ * 4) + 512, _g + _i * V_ + 128);       \
        }                                                                \
        cpa_commit();                                                    \
    } while (0)

    if (warp == 1) {
        // ================= PRODUCER =================
#pragma unroll
        for (int c = 0; c < RING - 1; c++) ISSUE(c);   // prefill 0..2
#pragma unroll 1
        for (int c = 0; c < NCHUNK; c++) {
            const int rem = NCHUNK - 1 - c;
            cpa_wait(rem > RING - 2 ? RING - 2 : rem); // chunk c landed
            barrier64();                               // publish chunk c
            if (c + RING - 1 < NCHUNK) ISSUE(c + RING - 1); // overwrites slot (c-1)%RING
        }
        return;
    }

    // ================= CONSUMER (DP) =================
    const int lab0  = y_true[b * L_ + 2 * lane];
    const int lab1  = y_true[b * L_ + 2 * lane + 1];
    const int labm1 = __shfl_up_sync(FULL_, lab1, 1);
    const float sk1 = (lane == 0) ? 1.0f : ((lab0 != labm1) ? 1.0f : 0.0f);
    const float sk3 = (lab1 != lab0) ? 1.0f : 0.0f;

    float a0 = 0.f, a1 = 0.f, a2 = 0.f, a3 = 0.f, a4 = 0.f;
    int   E  = 0;
    float s1 = (lane == 0) ? 0.f : 1.f, s2 = 1.f;

#define STEP(pvb, pv1, pv3) do {                                   \
        const float _pb = (pvb) + EPS_;                            \
        const float _p1 = (pv1) + EPS_;                            \
        const float _p3 = (pv3) + EPS_;                            \
        const float a3p = __shfl_up_sync(FULL_, a3, 1);            \
        const float a3q = (a3p * s1) * s2;                         \
        const float n0 = (a0 + a3q) * _pb;                         \
        const float n1 = fmaf(sk1, a3q, a0 + a1) * _p1;            \
        const float n2 = (a1 + a2) * _pb;                          \
        const float n3 = fmaf(sk3, a1, a2 + a3) * _p3;             \
        const float n4 = (a3 + a4) * _pb;                          \
        a0 = n0; a1 = n1; a2 = n2; a3 = n3; a4 = n4;               \
    } while (0)

#define NEIGHBOR_FACTORS() do {                                    \
        const int Ep = __shfl_up_sync(FULL_, E, 1);                \
        const int dE = Ep - E;                                     \
        const int d1 = dE >> 1, d2 = dE - d1;                      \
        s1 = (lane == 0) ? 0.f : exp2i_clamped(d1);                \
        s2 = exp2i_clamped(d2);                                    \
    } while (0)

#define RESCALE_SCAN() do {                                        \
        float m = fmaxf(fmaxf(a0, a1), fmaxf(a2, a3));             \
        m = fmaxf(m, a4);                                          \
        const bool nz = (m > 0.f);                                 \
        if (nz) {                                                  \
            const int e  = ilogbf(m);                              \
            const int h1 = e >> 1, h2 = e - h1;                    \
            const float u1 = exp2i_clamped(-h1);                   \
            const float u2 = exp2i_clamped(-h2);                   \
            a0 = (a0 * u1) * u2; a1 = (a1 * u1) * u2;              \
            a2 = (a2 * u1) * u2; a3 = (a3 * u1) * u2;              \
            a4 = (a4 * u1) * u2;                                   \
            E += e;                                                \
        }                                                          \
        int key = nz ? ((lane << 15) | (E + 16384)) : -1;          \
        _Pragma("unroll")                                          \
        for (int off = 1; off < 32; off <<= 1) {                   \
            const int kl = __shfl_up_sync(FULL_, key, off);        \
            if (lane >= off) key = max(key, kl);                   \
        }                                                          \
        if (!nz) E = (key & 32767) - 16384;                        \
        NEIGHBOR_FACTORS();                                        \
    } while (0)

#define RESCALE_FAST() do {                                        \
        float m = fmaxf(fmaxf(a0, a1), fmaxf(a2, a3));             \
        m = fmaxf(m, a4);                                          \
        const int e  = ilogbf(m);                                  \
        const int h1 = e >> 1, h2 = e - h1;                        \
        const float u1 = exp2i_clamped(-h1);                       \
        const float u2 = exp2i_clamped(-h2);                       \
        a0 = (a0 * u1) * u2; a1 = (a1 * u1) * u2;                  \
        a2 = (a2 * u1) * u2; a3 = (a3 * u1) * u2;                  \
        a4 = (a4 * u1) * u2;                                       \
        E += e;                                                    \
        NEIGHBOR_FACTORS();                                        \
    } while (0)

#define GATHER(c, v1, v3, vb) do {                                 \
        const int _slot = (c) & (RING - 1);                        \
        _Pragma("unroll")                                          \
        for (int _i = 0; _i < CHUNK; _i++) {                       \
            (v1)[_i] = ROW[_slot][_i][lab0];                       \
            (v3)[_i] = ROW[_slot][_i][lab1];                       \
            (vb)[_i] = ROW[_slot][_i][BLANK_];                     \
        }                                                          \
    } while (0)

#define PROC8(v1, v3, vb) do {                                     \
        _Pragma("unroll")                                          \
        for (int _i = 0; _i < CHUNK; _i++)                         \
            STEP((vb)[_i], (v1)[_i], (v3)[_i]);                    \
    } while (0)

    float A1[CHUNK], A3[CHUNK], Ab[CHUNK];
    float B1[CHUNK], B3[CHUNK], Bb[CHUNK];

    // ---- prologue: gather chunk0 into A, chunk1 into B, run chunk0 ----
    barrier64(); GATHER(0, A1, A3, Ab);
    barrier64(); GATHER(1, B1, B3, Bb);
    a0 = (lane == 0) ? (Ab[0] + EPS_) : 0.f;
    a1 = (lane == 0) ? (A1[0] + EPS_) : 0.f;
#pragma unroll
    for (int i = 1; i < CHUNK; i++) STEP(Ab[i], A1[i], A3[i]);
    RESCALE_SCAN();

    // ---- startup chunks 1..7 (frontier scan), alternating buffers ----
    barrier64(); GATHER(2, A1, A3, Ab); PROC8(B1, B3, Bb); RESCALE_SCAN(); // chunk1
    barrier64(); GATHER(3, B1, B3, Bb); PROC8(A1, A3, Ab); RESCALE_SCAN(); // chunk2
    barrier64(); GATHER(4, A1, A3, Ab); PROC8(B1, B3, Bb); RESCALE_SCAN(); // chunk3
    barrier64(); GATHER(5, B1, B3, Bb); PROC8(A1, A3, Ab); RESCALE_SCAN(); // chunk4
    barrier64(); GATHER(6, A1, A3, Ab); PROC8(B1, B3, Bb); RESCALE_SCAN(); // chunk5
    barrier64(); GATHER(7, B1, B3, Bb); PROC8(A1, A3, Ab); RESCALE_SCAN(); // chunk6
    barrier64(); GATHER(8, A1, A3, Ab); PROC8(B1, B3, Bb); RESCALE_SCAN(); // chunk7

    // ---- steady state: chunks 8..61 (A currently holds chunk 8) ----
#pragma unroll 1
    for (int c = 9; c <= 61; c += 2) {
        barrier64(); GATHER(c,     B1, B3, Bb); PROC8(A1, A3, Ab); RESCALE_FAST(); // chunk c-1
        barrier64(); GATHER(c + 1, A1, A3, Ab); PROC8(B1, B3, Bb); RESCALE_FAST(); // chunk c
    }

    // ---- tail: A holds chunk 62, gather+run 63 ----
    barrier64(); GATHER(63, B1, B3, Bb); PROC8(A1, A3, Ab); RESCALE_FAST(); // chunk62
    PROC8(B1, B3, Bb);                                                      // chunk63

    // loss = -( log(alpha[127] + alpha[128]) + E*ln2 ), both on lane 31
    if (lane == 31) {
        const float tot = a3 + a4;
        out[b] = -(logf(tot) + (float)E * 0.6931471805599453f);
    }

#undef STEP
#undef NEIGHBOR_FACTORS
#undef RESCALE_SCAN
#undef RESCALE_FAST
#undef GATHER
#undef PROC8
#undef ISSUE
}

extern "C" void kernel_launch(void* const* d_in, const int* in_sizes, int n_in,
                              void* d_out, int out_size) {
    const int*   y_true = (const int*)  d_in[0];
    const float* y_pred = (const float*)d_in[1];
    float*       out    = (float*)      d_out;
    ctc_kernel<<<B_, 64>>>(y_true, y_pred, out);
}

// round 15
// speedup vs baseline: 1.5831x; 1.0807x over previous
#include <cuda_runtime.h>
#include <cstdint>

// CTC batch cost (Keras ctc_batch_cost), blank = V-1.
// B=256, T=512, V=256, L=64, S=129.
//
// R15: warp-specialized CTA (64 threads), dynamic-smem 8-deep ring of full
// 1KB rows (cp.async.cg, coalesced). Producer ALSO performs the conflicted
// per-step gather (lab0/lab1/blank) into a compact 2-slot buffer; consumer
// reads conflict-free LDS.64 + broadcasts and runs the probability-domain DP
// with per-lane power-of-2 frames. ilogbf replaced by exponent-bit extract.

#define B_      256
#define T_      512
#define V_      256
#define L_      64
#define BLANK_  (V_ - 1)
#define EPS_    1e-7f
#define FULL_   0xffffffffu
#define CHUNK   8
#define RING    8
#define NCHUNK  (T_ / CHUNK)   // 64

// dynamic smem: ROW ring + compact (q1,q3) + compact blank
#define ROW_FLOATS   (RING * CHUNK * V_)            // 16384 floats = 64KB
#define C2_OFF       ROW_FLOATS                      // float2[2][CHUNK][32]
#define C2_FLOATS    (2 * CHUNK * 32 * 2)            // 1024 floats = 4KB
#define CB_OFF       (C2_OFF + C2_FLOATS)            // float[2][CHUNK]
#define SMEM_BYTES   ((ROW_FLOATS + C2_FLOATS + 2 * CHUNK) * 4)

__device__ __forceinline__ uint32_t smem_u32(const void* p) {
    return (uint32_t)__cvta_generic_to_shared(p);
}
__device__ __forceinline__ void cpa16(uint32_t s, const float* g) {
    asm volatile("cp.async.cg.shared.global [%0], [%1], 16;" :: "r"(s), "l"(g));
}
__device__ __forceinline__ void cpa_commit() {
    asm volatile("cp.async.commit_group;" ::: "memory");
}
__device__ __forceinline__ void cpa_wait(int n) {
    switch (n) {
      case 0: asm volatile("cp.async.wait_group 0;" ::: "memory"); break;
      case 1: asm volatile("cp.async.wait_group 1;" ::: "memory"); break;
      case 2: asm volatile("cp.async.wait_group 2;" ::: "memory"); break;
      case 3: asm volatile("cp.async.wait_group 3;" ::: "memory"); break;
      case 4: asm volatile("cp.async.wait_group 4;" ::: "memory"); break;
      case 5: asm volatile("cp.async.wait_group 5;" ::: "memory"); break;
      default: asm volatile("cp.async.wait_group 6;" ::: "memory"); break;
    }
}
__device__ __forceinline__ void barrier64() {
    asm volatile("bar.sync 0, 64;" ::: "memory");
}
__device__ __forceinline__ float exp2i_clamped(int k) {
    k = max(-126, min(127, k));
    return __int_as_float((k + 127) << 23);
}
// exponent of a positive float (normal range); denormals clamp to -127
__device__ __forceinline__ int expo(float m) {
    return ((__float_as_int(m) >> 23) & 0xff) - 127;
}

__global__ __launch_bounds__(64)
void ctc_kernel(const int* __restrict__ y_true,
                const float* __restrict__ y_pred,
                float* __restrict__ out)
{
    extern __shared__ float dsm[];
    float*  const ROWp = dsm;                       // [RING][CHUNK][V_]
    float2* const C2   = (float2*)(dsm + C2_OFF);   // [2][CHUNK][32]
    float*  const CB   = dsm + CB_OFF;              // [2][CHUNK]

    const int b    = blockIdx.x;
    const int lane = threadIdx.x & 31;
    const int warp = threadIdx.x >> 5;

    const float* __restrict__ base = y_pred + (size_t)b * (T_ * V_);
    const uint32_t sROW = smem_u32(ROWp);

    // labels (both warps need them; producer gathers with them)
    const int lab0 = y_true[b * L_ + 2 * lane];
    const int lab1 = y_true[b * L_ + 2 * lane + 1];

#define ISSUE(c) do {                                                    \
        const int _slot = (c) & (RING - 1);                              \
        const float* _g = base + (c) * (CHUNK * V_) + lane * 4;          \
        const uint32_t _dst = sROW + _slot * (CHUNK * V_ * 4) + lane*16; \
        _Pragma("unroll")                                                \
        for (int _i = 0; _i < CHUNK; _i++) {                             \
            cpa16(_dst + _i * (V_ * 4) + 0,   _g + _i * V_);             \
            cpa16(_dst + _i * (V_ * 4) + 512, _g + _i * V_ + 128);       \
        }                                                                \
        cpa_commit();                                                    \
    } while (0)

    if (warp == 1) {
        // ================= PRODUCER =================
#pragma unroll
        for (int c = 0; c < RING - 1; c++) ISSUE(c);   // prefill 0..6
#pragma unroll 1
        for (int c = 0; c < NCHUNK; c++) {
            const int rem = NCHUNK - 1 - c;
            cpa_wait(rem > RING - 2 ? RING - 2 : rem); // ROW chunk c landed
            // gather chunk c (conflicted LDS) -> compact slot c&1
            {
                const int rs = c & (RING - 1), cs = c & 1;
                const float* rbase = ROWp + rs * (CHUNK * V_);
                float v1[CHUNK], v3[CHUNK];
#pragma unroll
                for (int i = 0; i < CHUNK; i++) {
                    v1[i] = rbase[i * V_ + lab0];
                    v3[i] = rbase[i * V_ + lab1];
                }
#pragma unroll
                for (int i = 0; i < CHUNK; i++)
                    C2[(cs * CHUNK + i) * 32 + lane] = make_float2(v1[i], v3[i]);
                if (lane < CHUNK)
                    CB[cs * CHUNK + lane] = rbase[lane * V_ + BLANK_];
            }
            barrier64();                               // publish compact c
            if (c + RING - 1 < NCHUNK) ISSUE(c + RING - 1); // slot (c-1)%RING, already consumed
        }
        return;
    }

    // ================= CONSUMER (DP) =================
    const int labm1 = __shfl_up_sync(FULL_, lab1, 1);
    const float sk1 = (lane == 0) ? 1.0f : ((lab0 != labm1) ? 1.0f : 0.0f);
    const float sk3 = (lab1 != lab0) ? 1.0f : 0.0f;

    float a0 = 0.f, a1 = 0.f, a2 = 0.f, a3 = 0.f, a4 = 0.f;
    int   E  = 0;
    float s1 = (lane == 0) ? 0.f : 1.f, s2 = 1.f;

#define STEP(pvb, pv1, pv3) do {                                   \
        const float _pb = (pvb) + EPS_;                            \
        const float _p1 = (pv1) + EPS_;                            \
        const float _p3 = (pv3) + EPS_;                            \
        const float a3p = __shfl_up_sync(FULL_, a3, 1);            \
        const float a3q = (a3p * s1) * s2;                         \
        const float n0 = (a0 + a3q) * _pb;                         \
        const float n1 = fmaf(sk1, a3q, a0 + a1) * _p1;            \
        const float n2 = (a1 + a2) * _pb;                          \
        const float n3 = fmaf(sk3, a1, a2 + a3) * _p3;             \
        const float n4 = (a3 + a4) * _pb;                          \
        a0 = n0; a1 = n1; a2 = n2; a3 = n3; a4 = n4;               \
    } while (0)

#define NEIGHBOR_FACTORS() do {                                    \
        const int Ep = __shfl_up_sync(FULL_, E, 1);                \
        const int dE = Ep - E;                                     \
        const int d1 = dE >> 1, d2 = dE - d1;                      \
        s1 = (lane == 0) ? 0.f : exp2i_clamped(d1);                \
        s2 = exp2i_clamped(d2);                                    \
    } while (0)

#define RESCALE_SCAN() do {                                        \
        float m = fmaxf(fmaxf(a0, a1), fmaxf(a2, a3));             \
        m = fmaxf(m, a4);                                          \
        const bool nz = (m > 0.f);                                 \
        if (nz) {                                                  \
            const int e  = expo(m);                                \
            const int h1 = e >> 1, h2 = e - h1;                    \
            const float u1 = exp2i_clamped(-h1);                   \
            const float u2 = exp2i_clamped(-h2);                   \
            a0 = (a0 * u1) * u2; a1 = (a1 * u1) * u2;              \
            a2 = (a2 * u1) * u2; a3 = (a3 * u1) * u2;              \
            a4 = (a4 * u1) * u2;                                   \
            E += e;                                                \
        }                                                          \
        int key = nz ? ((lane << 15) | (E + 16384)) : -1;          \
        _Pragma("unroll")                                          \
        for (int off = 1; off < 32; off <<= 1) {                   \
            const int kl = __shfl_up_sync(FULL_, key, off);        \
            if (lane >= off) key = max(key, kl);                   \
        }                                                          \
        if (!nz) E = (key & 32767) - 16384;                        \
        NEIGHBOR_FACTORS();                                        \
    } while (0)

#define RESCALE_FAST() do {                                        \
        float m = fmaxf(fmaxf(a0, a1), fmaxf(a2, a3));             \
        m = fmaxf(m, a4);                                          \
        const int e  = expo(m);                                    \
        const int h1 = e >> 1, h2 = e - h1;                        \
        const float u1 = exp2i_clamped(-h1);                       \
        const float u2 = exp2i_clamped(-h2);                       \
        a0 = (a0 * u1) * u2; a1 = (a1 * u1) * u2;                  \
        a2 = (a2 * u1) * u2; a3 = (a3 * u1) * u2;                  \
        a4 = (a4 * u1) * u2;                                       \
        E += e;                                                    \
        NEIGHBOR_FACTORS();                                        \
    } while (0)

    // conflict-free compact read: 8x LDS.64 + 8x broadcast
#define GATHERC(c, v1, v3, vb) do {                                \
        const int _cs = (c) & 1;                                   \
        _Pragma("unroll")                                          \
        for (int _i = 0; _i < CHUNK; _i++) {                       \
            const float2 _t = C2[(_cs * CHUNK + _i) * 32 + lane];  \
            (v1)[_i] = _t.x; (v3)[_i] = _t.y;                      \
            (vb)[_i] = CB[_cs * CHUNK + _i];                       \
        }                                                          \
    } while (0)

#define PROC8(v1, v3, vb) do {                                     \
        _Pragma("unroll")                                          \
        for (int _i = 0; _i < CHUNK; _i++)                         \
            STEP((vb)[_i], (v1)[_i], (v3)[_i]);                    \
    } while (0)

    float v1[CHUNK], v3[CHUNK], vb[CHUNK];

    // ---- chunk 0 ----
    barrier64();
    GATHERC(0, v1, v3, vb);
    a0 = (lane == 0) ? (vb[0] + EPS_) : 0.f;
    a1 = (lane == 0) ? (v1[0] + EPS_) : 0.f;
#pragma unroll
    for (int i = 1; i < CHUNK; i++) STEP(vb[i], v1[i], v3[i]);
    RESCALE_SCAN();

    // ---- startup chunks 1..7 (frontier scan) ----
#pragma unroll 1
    for (int c = 1; c < 8; c++) {
        barrier64();
        GATHERC(c, v1, v3, vb);
        PROC8(v1, v3, vb);
        RESCALE_SCAN();
    }

    // ---- steady state: chunks 8..62 ----
#pragma unroll 1
    for (int c = 8; c < NCHUNK - 1; c++) {
        barrier64();
        GATHERC(c, v1, v3, vb);
        PROC8(v1, v3, vb);
        RESCALE_FAST();
    }

    // ---- last chunk 63 ----
    barrier64();
    GATHERC(NCHUNK - 1, v1, v3, vb);
    PROC8(v1, v3, vb);

    // loss = -( log(alpha[127] + alpha[128]) + E*ln2 ), both on lane 31
    if (lane == 31) {
        const float tot = a3 + a4;
        out[b] = -(logf(tot) + (float)E * 0.6931471805599453f);
    }

#undef STEP
#undef NEIGHBOR_FACTORS
#undef RESCALE_SCAN
#undef RESCALE_FAST
#undef GATHERC
#undef PROC8
#undef ISSUE
}

extern "C" void kernel_launch(void* const* d_in, const int* in_sizes, int n_in,
                              void* d_out, int out_size) {
    const int*   y_true = (const int*)  d_in[0];
    const float* y_pred = (const float*)d_in[1];
    float*       out    = (float*)      d_out;
    static bool attr_set = false;
    if (!attr_set) {
        cudaFuncSetAttribute(ctc_kernel,
                             cudaFuncAttributeMaxDynamicSharedMemorySize,
                             SMEM_BYTES);
        attr_set = true;
    }
    ctc_kernel<<<B_, 64, SMEM_BYTES>>>(y_true, y_pred, out);
}

// round 16
// speedup vs baseline: 1.6518x; 1.0434x over previous
#include <cuda_runtime.h>
#include <cstdint>

// CTC batch cost (Keras ctc_batch_cost), blank = V-1.
// B=256, T=512, V=256, L=64, S=129.
//
// R16: TWO batch elements per CTA (128 CTAs -> at most 1 CTA/SM, balanced;
// R15's 256 CTAs left 108 SMs doubled and 40 half-loaded). Block = 128 thr:
// warp p   (p=0,1) = DP consumer for element 2*blockIdx.x + p
// warp p+2         = its producer (cp.async.cg full-1KB-row 8-deep ring +
//                    conflicted smem gather into a compact 2-slot buffer).
// Each pair paces itself with its own named barrier (bar.sync p+1, 64), so
// the two streams are independent. DP: probability domain, per-lane
// power-of-2 frames, frontier scan only for t<64.

#define B_      256
#define T_      512
#define V_      256
#define L_      64
#define BLANK_  (V_ - 1)
#define EPS_    1e-7f
#define FULL_   0xffffffffu
#define CHUNK   8
#define RING    8
#define NCHUNK  (T_ / CHUNK)   // 64

// per-pair dynamic smem region (floats)
#define ROW_FLOATS   (RING * CHUNK * V_)             // 16384 floats = 64KB
#define C2_OFF       ROW_FLOATS                      // float2[2][CHUNK][32]
#define C2_FLOATS    (2 * CHUNK * 32 * 2)            // 1024 floats = 4KB
#define CB_OFF       (C2_OFF + C2_FLOATS)            // float[2][CHUNK]
#define PAIR_FLOATS  (ROW_FLOATS + C2_FLOATS + 2 * CHUNK)
#define SMEM_BYTES   (2 * PAIR_FLOATS * 4)

__device__ __forceinline__ uint32_t smem_u32(const void* p) {
    return (uint32_t)__cvta_generic_to_shared(p);
}
__device__ __forceinline__ void cpa16(uint32_t s, const float* g) {
    asm volatile("cp.async.cg.shared.global [%0], [%1], 16;" :: "r"(s), "l"(g));
}
__device__ __forceinline__ void cpa_commit() {
    asm volatile("cp.async.commit_group;" ::: "memory");
}
__device__ __forceinline__ void cpa_wait(int n) {
    switch (n) {
      case 0: asm volatile("cp.async.wait_group 0;" ::: "memory"); break;
      case 1: asm volatile("cp.async.wait_group 1;" ::: "memory"); break;
      case 2: asm volatile("cp.async.wait_group 2;" ::: "memory"); break;
      case 3: asm volatile("cp.async.wait_group 3;" ::: "memory"); break;
      case 4: asm volatile("cp.async.wait_group 4;" ::: "memory"); break;
      case 5: asm volatile("cp.async.wait_group 5;" ::: "memory"); break;
      default: asm volatile("cp.async.wait_group 6;" ::: "memory"); break;
    }
}
// named barrier per element pair: warps {p, p+2}, 64 threads
__device__ __forceinline__ void barrier_pair(int pair) {
    asm volatile("bar.sync %0, 64;" :: "r"(pair + 1) : "memory");
}
__device__ __forceinline__ float exp2i_clamped(int k) {
    k = max(-126, min(127, k));
    return __int_as_float((k + 127) << 23);
}
__device__ __forceinline__ int expo(float m) {
    return ((__float_as_int(m) >> 23) & 0xff) - 127;
}

__global__ __launch_bounds__(128)
void ctc_kernel(const int* __restrict__ y_true,
                const float* __restrict__ y_pred,
                float* __restrict__ out)
{
    extern __shared__ float dsm[];

    const int lane = threadIdx.x & 31;
    const int warp = threadIdx.x >> 5;
    const int pair = warp & 1;            // element within the CTA
    const bool is_producer = (warp >= 2);

    const int b = blockIdx.x * 2 + pair;

    float*  const PR   = dsm + pair * PAIR_FLOATS;
    float*  const ROWp = PR;                        // [RING][CHUNK][V_]
    float2* const C2   = (float2*)(PR + C2_OFF);    // [2][CHUNK][32]
    float*  const CB   = PR + CB_OFF;               // [2][CHUNK]

    const float* __restrict__ base = y_pred + (size_t)b * (T_ * V_);
    const uint32_t sROW = smem_u32(ROWp);

    const int lab0 = y_true[b * L_ + 2 * lane];
    const int lab1 = y_true[b * L_ + 2 * lane + 1];

#define ISSUE(c) do {                                                    \
        const int _slot = (c) & (RING - 1);                              \
        const float* _g = base + (c) * (CHUNK * V_) + lane * 4;          \
        const uint32_t _dst = sROW + _slot * (CHUNK * V_ * 4) + lane*16; \
        _Pragma("unroll")                                                \
        for (int _i = 0; _i < CHUNK; _i++) {                             \
            cpa16(_dst + _i * (V_ * 4) + 0,   _g + _i * V_);             \
            cpa16(_dst + _i * (V_ * 4) + 512, _g + _i * V_ + 128);       \
        }                                                                \
        cpa_commit();                                                    \
    } while (0)

    if (is_producer) {
        // ================= PRODUCER =================
#pragma unroll
        for (int c = 0; c < RING - 1; c++) ISSUE(c);   // prefill 0..6
#pragma unroll 1
        for (int c = 0; c < NCHUNK; c++) {
            const int rem = NCHUNK - 1 - c;
            cpa_wait(rem > RING - 2 ? RING - 2 : rem); // ROW chunk c landed
            {   // conflicted gather chunk c -> compact slot c&1
                const int rs = c & (RING - 1), cs = c & 1;
                const float* rbase = ROWp + rs * (CHUNK * V_);
                float v1[CHUNK], v3[CHUNK];
#pragma unroll
                for (int i = 0; i < CHUNK; i++) {
                    v1[i] = rbase[i * V_ + lab0];
                    v3[i] = rbase[i * V_ + lab1];
                }
#pragma unroll
                for (int i = 0; i < CHUNK; i++)
                    C2[(cs * CHUNK + i) * 32 + lane] = make_float2(v1[i], v3[i]);
                if (lane < CHUNK)
                    CB[cs * CHUNK + lane] = rbase[lane * V_ + BLANK_];
            }
            barrier_pair(pair);                        // publish compact c
            if (c + RING - 1 < NCHUNK) ISSUE(c + RING - 1);
        }
        return;
    }

    // ================= CONSUMER (DP) =================
    const int labm1 = __shfl_up_sync(FULL_, lab1, 1);
    const float sk1 = (lane == 0) ? 1.0f : ((lab0 != labm1) ? 1.0f : 0.0f);
    const float sk3 = (lab1 != lab0) ? 1.0f : 0.0f;

    float a0 = 0.f, a1 = 0.f, a2 = 0.f, a3 = 0.f, a4 = 0.f;
    int   E  = 0;
    float s1 = (lane == 0) ? 0.f : 1.f, s2 = 1.f;

#define STEP(pvb, pv1, pv3) do {                                   \
        const float _pb = (pvb) + EPS_;                            \
        const float _p1 = (pv1) + EPS_;                            \
        const float _p3 = (pv3) + EPS_;                            \
        const float a3p = __shfl_up_sync(FULL_, a3, 1);            \
        const float a3q = (a3p * s1) * s2;                         \
        const float n0 = (a0 + a3q) * _pb;                         \
        const float n1 = fmaf(sk1, a3q, a0 + a1) * _p1;            \
        const float n2 = (a1 + a2) * _pb;                          \
        const float n3 = fmaf(sk3, a1, a2 + a3) * _p3;             \
        const float n4 = (a3 + a4) * _pb;                          \
        a0 = n0; a1 = n1; a2 = n2; a3 = n3; a4 = n4;               \
    } while (0)

#define NEIGHBOR_FACTORS() do {                                    \
        const int Ep = __shfl_up_sync(FULL_, E, 1);                \
        const int dE = Ep - E;                                     \
        const int d1 = dE >> 1, d2 = dE - d1;                      \
        s1 = (lane == 0) ? 0.f : exp2i_clamped(d1);                \
        s2 = exp2i_clamped(d2);                                    \
    } while (0)

#define RESCALE_SCAN() do {                                        \
        float m = fmaxf(fmaxf(a0, a1), fmaxf(a2, a3));             \
        m = fmaxf(m, a4);                                          \
        const bool nz = (m > 0.f);                                 \
        if (nz) {                                                  \
            const int e  = expo(m);                                \
            const int h1 = e >> 1, h2 = e - h1;                    \
            const float u1 = exp2i_clamped(-h1);                   \
            const float u2 = exp2i_clamped(-h2);                   \
            a0 = (a0 * u1) * u2; a1 = (a1 * u1) * u2;              \
            a2 = (a2 * u1) * u2; a3 = (a3 * u1) * u2;              \
            a4 = (a4 * u1) * u2;                                   \
            E += e;                                                \
        }                                                          \
        int key = nz ? ((lane << 15) | (E + 16384)) : -1;          \
        _Pragma("unroll")                                          \
        for (int off = 1; off < 32; off <<= 1) {                   \
            const int kl = __shfl_up_sync(FULL_, key, off);        \
            if (lane >= off) key = max(key, kl);                   \
        }                                                          \
        if (!nz) E = (key & 32767) - 16384;                        \
        NEIGHBOR_FACTORS();                                        \
    } while (0)

#define RESCALE_FAST() do {                                        \
        float m = fmaxf(fmaxf(a0, a1), fmaxf(a2, a3));             \
        m = fmaxf(m, a4);                                          \
        const int e  = expo(m);                                    \
        const int h1 = e >> 1, h2 = e - h1;                        \
        const float u1 = exp2i_clamped(-h1);                       \
        const float u2 = exp2i_clamped(-h2);                       \
        a0 = (a0 * u1) * u2; a1 = (a1 * u1) * u2;                  \
        a2 = (a2 * u1) * u2; a3 = (a3 * u1) * u2;                  \
        a4 = (a4 * u1) * u2;                                       \
        E += e;                                                    \
        NEIGHBOR_FACTORS();                                        \
    } while (0)

#define GATHERC(c, v1, v3, vb) do {                                \
        const int _cs = (c) & 1;                                   \
        _Pragma("unroll")                                          \
        for (int _i = 0; _i < CHUNK; _i++) {                       \
            const float2 _t = C2[(_cs * CHUNK + _i) * 32 + lane];  \
            (v1)[_i] = _t.x; (v3)[_i] = _t.y;                      \
            (vb)[_i] = CB[_cs * CHUNK + _i];                       \
        }                                                          \
    } while (0)

#define PROC8(v1, v3, vb) do {                                     \
        _Pragma("unroll")                                          \
        for (int _i = 0; _i < CHUNK; _i++)                         \
            STEP((vb)[_i], (v1)[_i], (v3)[_i]);                    \
    } while (0)

    float v1[CHUNK], v3[CHUNK], vb[CHUNK];

    // ---- chunk 0 ----
    barrier_pair(pair);
    GATHERC(0, v1, v3, vb);
    a0 = (lane == 0) ? (vb[0] + EPS_) : 0.f;
    a1 = (lane == 0) ? (v1[0] + EPS_) : 0.f;
#pragma unroll
    for (int i = 1; i < CHUNK; i++) STEP(vb[i], v1[i], v3[i]);
    RESCALE_SCAN();

    // ---- startup chunks 1..7 (frontier scan) ----
#pragma unroll 1
    for (int c = 1; c < 8; c++) {
        barrier_pair(pair);
        GATHERC(c, v1, v3, vb);
        PROC8(v1, v3, vb);
        RESCALE_SCAN();
    }

    // ---- steady state: chunks 8..62 ----
#pragma unroll 1
    for (int c = 8; c < NCHUNK - 1; c++) {
        barrier_pair(pair);
        GATHERC(c, v1, v3, vb);
        PROC8(v1, v3, vb);
        RESCALE_FAST();
    }

    // ---- last chunk 63 ----
    barrier_pair(pair);
    GATHERC(NCHUNK - 1, v1, v3, vb);
    PROC8(v1, v3, vb);

    // loss = -( log(alpha[127] + alpha[128]) + E*ln2 ), both on lane 31
    if (lane == 31) {
        const float tot = a3 + a4;
        out[b] = -(logf(tot) + (float)E * 0.6931471805599453f);
    }

#undef STEP
#undef NEIGHBOR_FACTORS
#undef RESCALE_SCAN
#undef RESCALE_FAST
#undef GATHERC
#undef PROC8
#undef ISSUE
}

extern "C" void kernel_launch(void* const* d_in, const int* in_sizes, int n_in,
                              void* d_out, int out_size) {
    const int*   y_true = (const int*)  d_in[0];
    const float* y_pred = (const float*)d_in[1];
    float*       out    = (float*)      d_out;
    static bool attr_set = false;
    if (!attr_set) {
        cudaFuncSetAttribute(ctc_kernel,
                             cudaFuncAttributeMaxDynamicSharedMemorySize,
                             SMEM_BYTES);
        attr_set = true;
    }
    ctc_kernel<<<B_ / 2, 128, SMEM_BYTES>>>(y_true, y_pred, out);
}